// round 11
// baseline (speedup 1.0000x reference)
#include <cuda_runtime.h>
#include <cuda_bf16.h>
#include <mma.h>
#include <cstdint>

using namespace nvcuda;

#define T_ 8
#define N_ 50000
#define D_ 128
#define E_ 800000
#define L_ 2
#define SH_ 8
#define FH_ 16

// ---------------- scratch pool (static device memory; no allocs) ----------------
constexpr size_t BIG    = (size_t)T_ * N_ * D_;    // 51,200,000 floats
constexpr size_t SMALLV = (size_t)T_ * N_ * SH_;   // 3,200,000 floats
constexpr size_t RN     = (size_t)T_ * N_;         // 400,000 rows
constexpr size_t OFF_H    = 0;
constexpr size_t OFF_TI   = BIG;
constexpr size_t OFF_Q    = 2 * BIG;
constexpr size_t OFF_K    = 3 * BIG;
constexpr size_t OFF_V    = 4 * BIG;
constexpr size_t OFF_PS   = 5 * BIG;
constexpr size_t OFF_PD   = OFF_PS + SMALLV;
constexpr size_t OFF_CSR  = OFF_PD + SMALLV;               // int2 per edge
constexpr size_t OFF_OFFS = OFF_CSR + 2 * (size_t)T_ * E_; // int offsets [RN+1]
constexpr size_t OFF_CUR  = OFF_OFFS + RN + 8;
constexpr size_t OFF_BS   = OFF_CUR + RN + 8;
constexpr size_t OFF_BIMG = OFF_BS + 512;                  // 8 mats x (16384 hi + 16384 lo) bf16
constexpr size_t POOL_SZ  = OFF_BIMG + 131072;

__device__ __align__(256) float g_pool[POOL_SZ];

// ---------------- weight conversion: 8 matrices -> row-major [k][n] bf16 hi/lo ----------------
// g: 0..1 = GAT layer (B[k][n] = W_s[ell][n>>4][k][n&15]); 2+ell*3+{0,1,2} = Q/K/V (B[k][n] = W[ell][k][n])
__global__ void prep_bconv(const float* __restrict__ Ws_, const float* __restrict__ Wq,
                           const float* __restrict__ Wk, const float* __restrict__ Wv,
                           __nv_bfloat16* __restrict__ Bimg) {
    int i = blockIdx.x * 256 + threadIdx.x;            // < 131072 = 8*16384
    int g = i >> 14, idx = i & 16383;
    int k = idx >> 7, n = idx & 127;
    float val;
    if (g < 2) {
        val = Ws_[g * 16384 + (n >> 4) * 2048 + k * 16 + (n & 15)];
    } else {
        int m = g - 2, ell = m / 3, sel = m % 3;
        const float* W = sel == 0 ? Wq : (sel == 1 ? Wk : Wv);
        val = W[ell * 16384 + k * 128 + n];
    }
    __nv_bfloat16 hi = __float2bfloat16_rn(val);
    __nv_bfloat16 lo = __float2bfloat16_rn(val - __bfloat162float(hi));
    Bimg[(size_t)g * 32768 + idx] = hi;
    Bimg[(size_t)g * 32768 + 16384 + idx] = lo;
}

// ---------------- tensor-core GEMM via wmma (HMMA; tcgen05 blocked by compile target) -------
// C_m[400000][128] = X[400000][128] @ W_m[128][128], m < nmats (A converted once, B cycled).
// Split-fp32: D = Ahi*Bhi + Ahi*Blo + Alo*Bhi.
// Inner loop ordering: dependency distance 4 between same-accumulator MMAs with only
// 4 B fragments live at any point (bh group reused before bl group loads).
constexpr int LDA = 136;                               // padded smem leading dim (bf16 elems)
constexpr int GEMM_SMEM_BYTES = (2 * 64 * LDA + 2 * 128 * LDA) * 2;  // 104448

__global__ __launch_bounds__(256, 2) void gemm_w(const float* __restrict__ X,
                                                 const __nv_bfloat16* __restrict__ Bm,
                                                 float* __restrict__ C0,
                                                 float* __restrict__ C1,
                                                 float* __restrict__ C2,
                                                 int xmode, int nmats) {
    extern __shared__ __nv_bfloat16 sm[];
    __nv_bfloat16* Ah = sm;
    __nv_bfloat16* Al = Ah + 64 * LDA;
    __nv_bfloat16* Bh = Al + 64 * LDA;
    __nv_bfloat16* Bl = Bh + 128 * LDA;
    const int tid = threadIdx.x;

    // A tile: load 64 rows fp32, convert to bf16 hi/lo (once per CTA)
    size_t row0 = (size_t)blockIdx.x * 64;
    for (int p = tid; p < 2048; p += 256) {            // p = r*32 + c4
        int r = p >> 5, c4 = p & 31;
        size_t gr = row0 + r;
        size_t srow = xmode ? ((gr % N_) * T_ + gr / N_) : gr;
        float4 v = ((const float4*)X)[srow * 32 + c4];
        __nv_bfloat16 h0 = __float2bfloat16_rn(v.x), h1 = __float2bfloat16_rn(v.y);
        __nv_bfloat16 h2 = __float2bfloat16_rn(v.z), h3 = __float2bfloat16_rn(v.w);
        __nv_bfloat162 hp0(h0, h1), hp1(h2, h3);
        __nv_bfloat162 lp0 = __floats2bfloat162_rn(v.x - __bfloat162float(h0),
                                                   v.y - __bfloat162float(h1));
        __nv_bfloat162 lp1 = __floats2bfloat162_rn(v.z - __bfloat162float(h2),
                                                   v.w - __bfloat162float(h3));
        uint2 hw, lw;
        hw.x = *(uint32_t*)&hp0; hw.y = *(uint32_t*)&hp1;
        lw.x = *(uint32_t*)&lp0; lw.y = *(uint32_t*)&lp1;
        *(uint2*)(Ah + r * LDA + c4 * 4) = hw;
        *(uint2*)(Al + r * LDA + c4 * 4) = lw;
    }

    // warp w: row-block rb = w>>1 (16 rows), col-half ch = w&1 (4 x 16-col blocks)
    int w = tid >> 5;
    int rb = w >> 1, ch = w & 1;

    for (int m = 0; m < nmats; m++) {
        // B_m hi/lo -> smem (row-major [k][128], padded rows)
        const uint4* bsrc = (const uint4*)(Bm + (size_t)m * 32768);
        for (int p = tid; p < 2048; p += 256) {        // p = k*16 + c (8 bf16 per uint4)
            int k = p >> 4, c = p & 15;
            *(uint4*)(Bh + k * LDA + c * 8) = bsrc[p];
            *(uint4*)(Bl + k * LDA + c * 8) = bsrc[2048 + p];
        }
        __syncthreads();

        wmma::fragment<wmma::accumulator, 16, 16, 16, float> acc[4];
#pragma unroll
        for (int j = 0; j < 4; j++) wmma::fill_fragment(acc[j], 0.f);

#pragma unroll
        for (int ks = 0; ks < 8; ks++) {
            wmma::fragment<wmma::matrix_a, 16, 16, 16, __nv_bfloat16, wmma::row_major> ah, al;
            wmma::load_matrix_sync(ah, Ah + (rb * 16) * LDA + ks * 16, LDA);
            wmma::load_matrix_sync(al, Al + (rb * 16) * LDA + ks * 16, LDA);

            // Phase 1: load all 4 Bhi fragments (4 live)
            wmma::fragment<wmma::matrix_b, 16, 16, 16, __nv_bfloat16, wmma::row_major> bh[4];
#pragma unroll
            for (int cb = 0; cb < 4; cb++)
                wmma::load_matrix_sync(bh[cb], Bh + (ks * 16) * LDA + ch * 64 + cb * 16, LDA);
            // Group 1: 4 independent MMAs (distance 4 within each acc chain)
#pragma unroll
            for (int cb = 0; cb < 4; cb++) wmma::mma_sync(acc[cb], ah, bh[cb], acc[cb]);
            // Group 2: reuse bh (acc chain distance = 4)
#pragma unroll
            for (int cb = 0; cb < 4; cb++) wmma::mma_sync(acc[cb], al, bh[cb], acc[cb]);
            // Phase 2: load Blo fragments (bh dead -> regs reused; loads overlap group 2)
            wmma::fragment<wmma::matrix_b, 16, 16, 16, __nv_bfloat16, wmma::row_major> bl[4];
#pragma unroll
            for (int cb = 0; cb < 4; cb++)
                wmma::load_matrix_sync(bl[cb], Bl + (ks * 16) * LDA + ch * 64 + cb * 16, LDA);
            // Group 3 (acc chain distance = 4)
#pragma unroll
            for (int cb = 0; cb < 4; cb++) wmma::mma_sync(acc[cb], ah, bl[cb], acc[cb]);
        }

        float* Cm = (m == 0) ? C0 : (m == 1 ? C1 : C2);
#pragma unroll
        for (int cb = 0; cb < 4; cb++) {
            wmma::store_matrix_sync(Cm + (row0 + rb * 16) * 128 + ch * 64 + cb * 16,
                                    acc[cb], 128, wmma::mem_row_major);
        }
        if (m + 1 < nmats) __syncthreads();            // protect B smem before next fill
    }
}

// ---------------- CSR build ----------------
__global__ void zero_int(int* __restrict__ p, int n) {
    int i = blockIdx.x * 256 + threadIdx.x;
    if (i < n) p[i] = 0;
}

__global__ void hist_kernel(const int* __restrict__ eidx, int* __restrict__ counts) {
    int gid = blockIdx.x * 256 + threadIdx.x;
    int t = gid / E_, e = gid - t * E_;
    int src = eidx[(size_t)t * 2 * E_ + e];
    atomicAdd(counts + t * N_ + src, 1);
}

__global__ __launch_bounds__(1024) void scan_block(const int* __restrict__ counts,
                                                   int* __restrict__ offs,
                                                   int* __restrict__ bsum) {
    __shared__ int s[1024];
    int tid = threadIdx.x;
    int i = blockIdx.x * 1024 + tid;
    int v = (i < (int)RN) ? counts[i] : 0;
    s[tid] = v;
    __syncthreads();
#pragma unroll
    for (int off = 1; off < 1024; off <<= 1) {
        int x = (tid >= off) ? s[tid - off] : 0;
        __syncthreads();
        s[tid] += x;
        __syncthreads();
    }
    if (i < (int)RN) offs[i] = s[tid] - v;
    if (tid == 1023) bsum[blockIdx.x] = s[1023];
}

__global__ __launch_bounds__(512) void scan_bsum(int* __restrict__ bsum, int nb) {
    __shared__ int s[512];
    int tid = threadIdx.x;
    int v = (tid < nb) ? bsum[tid] : 0;
    s[tid] = v;
    __syncthreads();
#pragma unroll
    for (int off = 1; off < 512; off <<= 1) {
        int x = (tid >= off) ? s[tid - off] : 0;
        __syncthreads();
        s[tid] += x;
        __syncthreads();
    }
    if (tid < nb) bsum[tid] = s[tid] - v;
}

__global__ void scan_add(int* __restrict__ offs, const int* __restrict__ bsum,
                         int* __restrict__ cursor) {
    int i = blockIdx.x * 256 + threadIdx.x;
    if (i < (int)RN) {
        int o = offs[i] + bsum[i >> 10];
        offs[i] = o;
        cursor[i] = o;
        if (i == 0) offs[RN] = T_ * E_;
    }
}

__global__ void scatter_kernel(const int* __restrict__ eidx, const float* __restrict__ evals,
                               int* __restrict__ cursor, int2* __restrict__ csr) {
    int gid = blockIdx.x * 256 + threadIdx.x;
    int t = gid / E_, e = gid - t * E_;
    const int* ei = eidx + (size_t)t * 2 * E_;
    int src = ei[e];
    int dst = ei[E_ + e];
    int pos = atomicAdd(cursor + t * N_ + src, 1);
    csr[pos] = make_int2(dst, __float_as_int(evals[(size_t)t * E_ + e]));
}

// ---------------- ps/pd ----------------
__global__ __launch_bounds__(256) void pspd_kernel(const float* __restrict__ H,
                                                   const float* __restrict__ a,
                                                   float* __restrict__ ps, float* __restrict__ pd) {
    int r = blockIdx.x * 8 + (threadIdx.x >> 5);
    int lane = threadIdx.x & 31;
    float4 hv = ((const float4*)H)[(size_t)r * 32 + lane];
    int h = lane >> 2, fo = (lane & 3) * 4;
    const float* ah = a + h * 32;
    float4 av = *(const float4*)(ah + fo);
    float4 bv = *(const float4*)(ah + 16 + fo);
    float s = hv.x * av.x + hv.y * av.y + hv.z * av.z + hv.w * av.w;
    float d = hv.x * bv.x + hv.y * bv.y + hv.z * bv.z + hv.w * bv.w;
    s += __shfl_xor_sync(0xffffffffu, s, 1);
    s += __shfl_xor_sync(0xffffffffu, s, 2);
    d += __shfl_xor_sync(0xffffffffu, d, 1);
    d += __shfl_xor_sync(0xffffffffu, d, 2);
    if ((lane & 3) == 0) { ps[r * 8 + h] = s; pd[r * 8 + h] = d; }
}

// ---------------- fused GAT aggregate + normalize + ELU + transpose + Wp -> ti ----------------
__global__ __launch_bounds__(256) void gat_agg_kernel(const int* __restrict__ offs,
                                                      const int2* __restrict__ csr,
                                                      const float* __restrict__ H,
                                                      const float* __restrict__ ps,
                                                      const float* __restrict__ pd,
                                                      const float* __restrict__ Wp,
                                                      float* __restrict__ ti) {
    int r = blockIdx.x * 8 + (threadIdx.x >> 5);
    int lane = threadIdx.x & 31;
    int h = lane >> 2;
    int t = r / N_;
    int n = r - t * N_;
    int beg = offs[r], end = offs[r + 1];
    float psv = __ldg(ps + r * 8 + h);
    float4 acc = make_float4(0.f, 0.f, 0.f, 0.f);
    float esum = 0.f;
    const int tbase = t * N_;

    int2 cur = csr[beg];
    for (int j = beg; j < end; j++) {
        int2 nxt = make_int2(0, 0);
        if (j + 1 < end) nxt = csr[j + 1];
        int rd = tbase + cur.x;
        float w = __int_as_float(cur.y);
        float pdv = __ldg(pd + rd * 8 + h);
        float4 hv = ((const float4*)H)[(size_t)rd * 32 + lane];
        float sc = w * (psv + pdv);
        sc = sc > 0.f ? sc : 0.2f * sc;
        float ev = __expf(sc);
        esum += ev;
        acc.x += ev * hv.x;
        acc.y += ev * hv.y;
        acc.z += ev * hv.z;
        acc.w += ev * hv.w;
        cur = nxt;
    }
    float inv = 1.f / esum;
    float4 wp = ((const float4*)Wp)[t * 32 + lane];
    float vx = acc.x * inv, vy = acc.y * inv, vz = acc.z * inv, vw = acc.w * inv;
    vx = vx > 0.f ? vx : expm1f(vx);
    vy = vy > 0.f ? vy : expm1f(vy);
    vz = vz > 0.f ? vz : expm1f(vz);
    vw = vw > 0.f ? vw : expm1f(vw);
    float4 o = make_float4(vx + wp.x, vy + wp.y, vz + wp.z, vw + wp.w);
    ((float4*)ti)[((size_t)n * T_ + t) * 32 + lane] = o;
}

// ---------------- temporal attention ----------------
__global__ __launch_bounds__(256) void attn_kernel(const float* __restrict__ Q,
                                                   const float* __restrict__ K,
                                                   const float* __restrict__ V,
                                                   const float* __restrict__ ti,
                                                   float* __restrict__ out) {
    __shared__ float sb[8][384];
    int warp = threadIdx.x >> 5, lane = threadIdx.x & 31;
    int task = blockIdx.x * 8 + warp;
    int n = task >> 3, h = task & 7;
    int t4 = lane >> 2;
    int r4 = (n * T_ + t4) * 32 + h * 4 + (lane & 3);
    float* sq = sb[warp];
    float* sk = sq + 128;
    float* sv = sq + 256;
    ((float4*)sq)[lane] = ((const float4*)Q)[(size_t)r4];
    ((float4*)sk)[lane] = ((const float4*)K)[(size_t)r4];
    ((float4*)sv)[lane] = ((const float4*)V)[(size_t)r4];
    __syncwarp();
    if (lane < 8) {
        int t = lane;
        float q[16];
#pragma unroll
        for (int j = 0; j < 16; j++) q[j] = sq[t * 16 + j];
        float p[8];
        float mx = -1e30f;
#pragma unroll
        for (int s = 0; s < 8; s++) {
            float d = 0.f;
#pragma unroll
            for (int j = 0; j < 16; j++) d += q[j] * sk[s * 16 + j];
            d *= 0.25f;
            p[s] = d;
            if (s <= t && d > mx) mx = d;
        }
        float sum = 0.f;
#pragma unroll
        for (int s = 0; s < 8; s++) {
            float e = (s <= t) ? __expf(p[s] - mx) : 0.f;
            p[s] = e;
            sum += e;
        }
        float inv = 1.f / sum;
        float o[16];
#pragma unroll
        for (int j = 0; j < 16; j++) o[j] = 0.f;
#pragma unroll
        for (int s = 0; s < 8; s++) {
            float e = p[s];
#pragma unroll
            for (int j = 0; j < 16; j++) o[j] += e * sv[s * 16 + j];
        }
        size_t base = (size_t)(n * T_ + t) * 128 + h * 16;
#pragma unroll
        for (int j4 = 0; j4 < 4; j4++) {
            float4 tv = ((const float4*)(ti + base))[j4];
            float4 ov = make_float4(o[j4 * 4 + 0] * inv + tv.x,
                                    o[j4 * 4 + 1] * inv + tv.y,
                                    o[j4 * 4 + 2] * inv + tv.z,
                                    o[j4 * 4 + 3] * inv + tv.w);
            ((float4*)(out + base))[j4] = ov;
        }
    }
}

// ---------------- host ----------------
extern "C" void kernel_launch(void* const* d_in, const int* in_sizes, int n_in,
                              void* d_out, int out_size) {
    const float* features  = (const float*)d_in[0];
    const int*   edge_idx  = (const int*)d_in[1];
    const float* edge_vals = (const float*)d_in[2];
    const float* W_s       = (const float*)d_in[3];
    const float* a_s       = (const float*)d_in[4];
    const float* Wq        = (const float*)d_in[5];
    const float* Wkk       = (const float*)d_in[6];
    const float* Wv        = (const float*)d_in[7];
    const float* Wp        = (const float*)d_in[8];
    float* out = (float*)d_out;

    float* pool = nullptr;
    cudaGetSymbolAddress((void**)&pool, g_pool);
    float* H   = pool + OFF_H;
    float* TI  = pool + OFF_TI;
    float* Qb  = pool + OFF_Q;
    float* Kb  = pool + OFF_K;
    float* Vb  = pool + OFF_V;
    float* ps  = pool + OFF_PS;
    float* pd  = pool + OFF_PD;
    int2*  csr    = (int2*)(pool + OFF_CSR);
    int*   offs   = (int*)(pool + OFF_OFFS);
    int*   cursor = (int*)(pool + OFF_CUR);
    int*   bsum   = (int*)(pool + OFF_BS);
    __nv_bfloat16* Bimg = (__nv_bfloat16*)(pool + OFF_BIMG);

    cudaFuncSetAttribute(gemm_w, cudaFuncAttributeMaxDynamicSharedMemorySize, GEMM_SMEM_BYTES);

    const int nb_scan = (int)((RN + 1023) / 1024);

    // launch order: capture index 3 = gemm_w single-mat (ncu profiles ~index 3)
    prep_bconv<<<512, 256>>>(W_s, Wq, Wkk, Wv, Bimg);                       // 0
    zero_int<<<(int)((RN + 255) / 256), 256>>>(cursor, (int)RN);            // 1
    hist_kernel<<<(T_ * E_) / 256, 256>>>(edge_idx, cursor);                // 2
    gemm_w<<<6250, 256, GEMM_SMEM_BYTES>>>(features, Bimg, H, nullptr, nullptr, 0, 1);  // 3
    scan_block<<<nb_scan, 1024>>>(cursor, offs, bsum);                      // 4
    scan_bsum<<<1, 512>>>(bsum, nb_scan);                                   // 5
    scan_add<<<(int)((RN + 255) / 256), 256>>>(offs, bsum, cursor);         // 6
    scatter_kernel<<<(T_ * E_) / 256, 256>>>(edge_idx, edge_vals, cursor, csr);  // 7

    for (int ell = 0; ell < L_; ell++) {
        if (ell) {
            gemm_w<<<6250, 256, GEMM_SMEM_BYTES>>>((const float*)out,
                                                   Bimg + (size_t)ell * 32768,
                                                   H, nullptr, nullptr, 1, 1);
        }
        pspd_kernel<<<50000, 256>>>(H, a_s + ell * 256, ps, pd);
        gat_agg_kernel<<<50000, 256>>>(offs, csr, H, ps, pd, Wp + ell * (T_ * D_), TI);
        // fused Q,K,V: A loaded/converted once, 3 B matrices cycled through smem
        gemm_w<<<6250, 256, GEMM_SMEM_BYTES>>>(TI, Bimg + (size_t)(2 + ell * 3) * 32768,
                                               Qb, Kb, Vb, 0, 3);
        attn_kernel<<<50000, 256>>>(Qb, Kb, Vb, TI, out);
    }
}

// round 12
// speedup vs baseline: 1.0348x; 1.0348x over previous
#include <cuda_runtime.h>
#include <cuda_bf16.h>
#include <mma.h>
#include <cstdint>

using namespace nvcuda;

#define T_ 8
#define N_ 50000
#define D_ 128
#define E_ 800000
#define L_ 2
#define SH_ 8
#define FH_ 16

// ---------------- scratch pool (static device memory; no allocs) ----------------
constexpr size_t BIG    = (size_t)T_ * N_ * D_;    // 51,200,000 floats
constexpr size_t SMALLV = (size_t)T_ * N_ * SH_;   // 3,200,000 floats
constexpr size_t RN     = (size_t)T_ * N_;         // 400,000 rows
constexpr size_t OFF_H    = 0;
constexpr size_t OFF_TI   = BIG;
constexpr size_t OFF_Q    = 2 * BIG;
constexpr size_t OFF_K    = 3 * BIG;
constexpr size_t OFF_V    = 4 * BIG;
constexpr size_t OFF_PS   = 5 * BIG;
constexpr size_t OFF_PD   = OFF_PS + SMALLV;
constexpr size_t OFF_CSR  = OFF_PD + SMALLV;               // int2 per edge
constexpr size_t OFF_OFFS = OFF_CSR + 2 * (size_t)T_ * E_; // int offsets [RN+1]
constexpr size_t OFF_CUR  = OFF_OFFS + RN + 8;
constexpr size_t OFF_BS   = OFF_CUR + RN + 8;
constexpr size_t OFF_BIMG = OFF_BS + 512;                  // 8 mats x (16384 hi + 16384 lo) bf16
constexpr size_t POOL_SZ  = OFF_BIMG + 131072;

__device__ __align__(256) float g_pool[POOL_SZ];

// ---------------- weight conversion: 8 matrices -> row-major [k][n] bf16 hi/lo ----------------
// g: 0..1 = GAT layer (B[k][n] = W_s[ell][n>>4][k][n&15]); 2+ell*3+{0,1,2} = Q/K/V (B[k][n] = W[ell][k][n])
__global__ void prep_bconv(const float* __restrict__ Ws_, const float* __restrict__ Wq,
                           const float* __restrict__ Wk, const float* __restrict__ Wv,
                           __nv_bfloat16* __restrict__ Bimg) {
    int i = blockIdx.x * 256 + threadIdx.x;            // < 131072 = 8*16384
    int g = i >> 14, idx = i & 16383;
    int k = idx >> 7, n = idx & 127;
    float val;
    if (g < 2) {
        val = Ws_[g * 16384 + (n >> 4) * 2048 + k * 16 + (n & 15)];
    } else {
        int m = g - 2, ell = m / 3, sel = m % 3;
        const float* W = sel == 0 ? Wq : (sel == 1 ? Wk : Wv);
        val = W[ell * 16384 + k * 128 + n];
    }
    __nv_bfloat16 hi = __float2bfloat16_rn(val);
    __nv_bfloat16 lo = __float2bfloat16_rn(val - __bfloat162float(hi));
    Bimg[(size_t)g * 32768 + idx] = hi;
    Bimg[(size_t)g * 32768 + 16384 + idx] = lo;
}

// ---------------- tensor-core GEMM via wmma (HMMA; tcgen05 blocked by compile target) -------
// C_m[400000][128] = X[400000][128] @ W_m[128][128], m < nmats (A converted once, B cycled).
// Split-fp32: D = Ahi*Bhi + Ahi*Blo + Alo*Bhi.
// Geometry: CTA tile 128x128, 512 threads, warp tile 32x32 (4 rb x 4 cq).
// MMA:frag-load ratio 1.5 (vs 1.2 before); regs ~80 -> no spills at (512,1).
constexpr int LDA = 136;                               // padded smem leading dim (bf16 elems)
constexpr int MROWS = 128;                             // CTA row tile
constexpr int GEMM_SMEM_BYTES = (2 * MROWS * LDA + 2 * 128 * LDA) * 2;  // 139264

__global__ __launch_bounds__(512, 1) void gemm_w(const float* __restrict__ X,
                                                 const __nv_bfloat16* __restrict__ Bm,
                                                 float* __restrict__ C0,
                                                 float* __restrict__ C1,
                                                 float* __restrict__ C2,
                                                 int xmode, int nmats) {
    extern __shared__ __nv_bfloat16 sm[];
    __nv_bfloat16* Ah = sm;
    __nv_bfloat16* Al = Ah + MROWS * LDA;
    __nv_bfloat16* Bh = Al + MROWS * LDA;
    __nv_bfloat16* Bl = Bh + 128 * LDA;
    const int tid = threadIdx.x;

    // A tile: load 128 rows fp32, convert to bf16 hi/lo (once per CTA)
    size_t row0 = (size_t)blockIdx.x * MROWS;
    for (int p = tid; p < MROWS * 32; p += 512) {      // p = r*32 + c4
        int r = p >> 5, c4 = p & 31;
        size_t gr = row0 + r;
        size_t srow = xmode ? ((gr % N_) * T_ + gr / N_) : gr;
        float4 v = ((const float4*)X)[srow * 32 + c4];
        __nv_bfloat16 h0 = __float2bfloat16_rn(v.x), h1 = __float2bfloat16_rn(v.y);
        __nv_bfloat16 h2 = __float2bfloat16_rn(v.z), h3 = __float2bfloat16_rn(v.w);
        __nv_bfloat162 hp0(h0, h1), hp1(h2, h3);
        __nv_bfloat162 lp0 = __floats2bfloat162_rn(v.x - __bfloat162float(h0),
                                                   v.y - __bfloat162float(h1));
        __nv_bfloat162 lp1 = __floats2bfloat162_rn(v.z - __bfloat162float(h2),
                                                   v.w - __bfloat162float(h3));
        uint2 hw, lw;
        hw.x = *(uint32_t*)&hp0; hw.y = *(uint32_t*)&hp1;
        lw.x = *(uint32_t*)&lp0; lw.y = *(uint32_t*)&lp1;
        *(uint2*)(Ah + r * LDA + c4 * 4) = hw;
        *(uint2*)(Al + r * LDA + c4 * 4) = lw;
    }

    // warp w: row-block rb = w>>2 (32 rows), col-quarter cq = w&3 (2 x 16-col blocks)
    int w = tid >> 5;
    int rb = w >> 2, cq = w & 3;
    const int arow0 = rb * 32;
    const int col0 = cq * 32;

    for (int m = 0; m < nmats; m++) {
        // B_m hi/lo -> smem (row-major [k][128], padded rows)
        const uint4* bsrc = (const uint4*)(Bm + (size_t)m * 32768);
        for (int p = tid; p < 2048; p += 512) {        // p = k*16 + c (8 bf16 per uint4)
            int k = p >> 4, c = p & 15;
            *(uint4*)(Bh + k * LDA + c * 8) = bsrc[p];
            *(uint4*)(Bl + k * LDA + c * 8) = bsrc[2048 + p];
        }
        __syncthreads();

        wmma::fragment<wmma::accumulator, 16, 16, 16, float> acc[2][2];
#pragma unroll
        for (int s = 0; s < 2; s++)
#pragma unroll
            for (int c = 0; c < 2; c++) wmma::fill_fragment(acc[s][c], 0.f);

#pragma unroll
        for (int ks = 0; ks < 8; ks++) {
            // A frags: two 16-row sub-blocks, hi and lo (4 live)
            wmma::fragment<wmma::matrix_a, 16, 16, 16, __nv_bfloat16, wmma::row_major> ah[2], al[2];
#pragma unroll
            for (int s = 0; s < 2; s++) {
                wmma::load_matrix_sync(ah[s], Ah + (arow0 + s * 16) * LDA + ks * 16, LDA);
                wmma::load_matrix_sync(al[s], Al + (arow0 + s * 16) * LDA + ks * 16, LDA);
            }
            // B hi frags (2 live)
            wmma::fragment<wmma::matrix_b, 16, 16, 16, __nv_bfloat16, wmma::row_major> bh[2];
#pragma unroll
            for (int c = 0; c < 2; c++)
                wmma::load_matrix_sync(bh[c], Bh + (ks * 16) * LDA + col0 + c * 16, LDA);
            // Group 1: ah x bh (4 independent)
#pragma unroll
            for (int s = 0; s < 2; s++)
#pragma unroll
                for (int c = 0; c < 2; c++) wmma::mma_sync(acc[s][c], ah[s], bh[c], acc[s][c]);
            // Group 2: al x bh (4 independent)
#pragma unroll
            for (int s = 0; s < 2; s++)
#pragma unroll
                for (int c = 0; c < 2; c++) wmma::mma_sync(acc[s][c], al[s], bh[c], acc[s][c]);
            // B lo frags (bh dead -> reuse)
            wmma::fragment<wmma::matrix_b, 16, 16, 16, __nv_bfloat16, wmma::row_major> bl[2];
#pragma unroll
            for (int c = 0; c < 2; c++)
                wmma::load_matrix_sync(bl[c], Bl + (ks * 16) * LDA + col0 + c * 16, LDA);
            // Group 3: ah x bl (4 independent)
#pragma unroll
            for (int s = 0; s < 2; s++)
#pragma unroll
                for (int c = 0; c < 2; c++) wmma::mma_sync(acc[s][c], ah[s], bl[c], acc[s][c]);
        }

        float* Cm = (m == 0) ? C0 : (m == 1 ? C1 : C2);
#pragma unroll
        for (int s = 0; s < 2; s++)
#pragma unroll
            for (int c = 0; c < 2; c++) {
                wmma::store_matrix_sync(Cm + (row0 + arow0 + s * 16) * 128 + col0 + c * 16,
                                        acc[s][c], 128, wmma::mem_row_major);
            }
        if (m + 1 < nmats) __syncthreads();            // protect B smem before next fill
    }
}

// ---------------- CSR build ----------------
__global__ void zero_int(int* __restrict__ p, int n) {
    int i = blockIdx.x * 256 + threadIdx.x;
    if (i < n) p[i] = 0;
}

__global__ void hist_kernel(const int* __restrict__ eidx, int* __restrict__ counts) {
    int gid = blockIdx.x * 256 + threadIdx.x;
    int t = gid / E_, e = gid - t * E_;
    int src = eidx[(size_t)t * 2 * E_ + e];
    atomicAdd(counts + t * N_ + src, 1);
}

__global__ __launch_bounds__(1024) void scan_block(const int* __restrict__ counts,
                                                   int* __restrict__ offs,
                                                   int* __restrict__ bsum) {
    __shared__ int s[1024];
    int tid = threadIdx.x;
    int i = blockIdx.x * 1024 + tid;
    int v = (i < (int)RN) ? counts[i] : 0;
    s[tid] = v;
    __syncthreads();
#pragma unroll
    for (int off = 1; off < 1024; off <<= 1) {
        int x = (tid >= off) ? s[tid - off] : 0;
        __syncthreads();
        s[tid] += x;
        __syncthreads();
    }
    if (i < (int)RN) offs[i] = s[tid] - v;
    if (tid == 1023) bsum[blockIdx.x] = s[1023];
}

__global__ __launch_bounds__(512) void scan_bsum(int* __restrict__ bsum, int nb) {
    __shared__ int s[512];
    int tid = threadIdx.x;
    int v = (tid < nb) ? bsum[tid] : 0;
    s[tid] = v;
    __syncthreads();
#pragma unroll
    for (int off = 1; off < 512; off <<= 1) {
        int x = (tid >= off) ? s[tid - off] : 0;
        __syncthreads();
        s[tid] += x;
        __syncthreads();
    }
    if (tid < nb) bsum[tid] = s[tid] - v;
}

__global__ void scan_add(int* __restrict__ offs, const int* __restrict__ bsum,
                         int* __restrict__ cursor) {
    int i = blockIdx.x * 256 + threadIdx.x;
    if (i < (int)RN) {
        int o = offs[i] + bsum[i >> 10];
        offs[i] = o;
        cursor[i] = o;
        if (i == 0) offs[RN] = T_ * E_;
    }
}

__global__ void scatter_kernel(const int* __restrict__ eidx, const float* __restrict__ evals,
                               int* __restrict__ cursor, int2* __restrict__ csr) {
    int gid = blockIdx.x * 256 + threadIdx.x;
    int t = gid / E_, e = gid - t * E_;
    const int* ei = eidx + (size_t)t * 2 * E_;
    int src = ei[e];
    int dst = ei[E_ + e];
    int pos = atomicAdd(cursor + t * N_ + src, 1);
    csr[pos] = make_int2(dst, __float_as_int(evals[(size_t)t * E_ + e]));
}

// ---------------- ps/pd ----------------
__global__ __launch_bounds__(256) void pspd_kernel(const float* __restrict__ H,
                                                   const float* __restrict__ a,
                                                   float* __restrict__ ps, float* __restrict__ pd) {
    int r = blockIdx.x * 8 + (threadIdx.x >> 5);
    int lane = threadIdx.x & 31;
    float4 hv = ((const float4*)H)[(size_t)r * 32 + lane];
    int h = lane >> 2, fo = (lane & 3) * 4;
    const float* ah = a + h * 32;
    float4 av = *(const float4*)(ah + fo);
    float4 bv = *(const float4*)(ah + 16 + fo);
    float s = hv.x * av.x + hv.y * av.y + hv.z * av.z + hv.w * av.w;
    float d = hv.x * bv.x + hv.y * bv.y + hv.z * bv.z + hv.w * bv.w;
    s += __shfl_xor_sync(0xffffffffu, s, 1);
    s += __shfl_xor_sync(0xffffffffu, s, 2);
    d += __shfl_xor_sync(0xffffffffu, d, 1);
    d += __shfl_xor_sync(0xffffffffu, d, 2);
    if ((lane & 3) == 0) { ps[r * 8 + h] = s; pd[r * 8 + h] = d; }
}

// ---------------- fused GAT aggregate + normalize + ELU + transpose + Wp -> ti ----------------
__global__ __launch_bounds__(256) void gat_agg_kernel(const int* __restrict__ offs,
                                                      const int2* __restrict__ csr,
                                                      const float* __restrict__ H,
                                                      const float* __restrict__ ps,
                                                      const float* __restrict__ pd,
                                                      const float* __restrict__ Wp,
                                                      float* __restrict__ ti) {
    int r = blockIdx.x * 8 + (threadIdx.x >> 5);
    int lane = threadIdx.x & 31;
    int h = lane >> 2;
    int t = r / N_;
    int n = r - t * N_;
    int beg = offs[r], end = offs[r + 1];
    float psv = __ldg(ps + r * 8 + h);
    float4 acc = make_float4(0.f, 0.f, 0.f, 0.f);
    float esum = 0.f;
    const int tbase = t * N_;

    int2 cur = csr[beg];
    for (int j = beg; j < end; j++) {
        int2 nxt = make_int2(0, 0);
        if (j + 1 < end) nxt = csr[j + 1];
        int rd = tbase + cur.x;
        float w = __int_as_float(cur.y);
        float pdv = __ldg(pd + rd * 8 + h);
        float4 hv = ((const float4*)H)[(size_t)rd * 32 + lane];
        float sc = w * (psv + pdv);
        sc = sc > 0.f ? sc : 0.2f * sc;
        float ev = __expf(sc);
        esum += ev;
        acc.x += ev * hv.x;
        acc.y += ev * hv.y;
        acc.z += ev * hv.z;
        acc.w += ev * hv.w;
        cur = nxt;
    }
    float inv = 1.f / esum;
    float4 wp = ((const float4*)Wp)[t * 32 + lane];
    float vx = acc.x * inv, vy = acc.y * inv, vz = acc.z * inv, vw = acc.w * inv;
    vx = vx > 0.f ? vx : expm1f(vx);
    vy = vy > 0.f ? vy : expm1f(vy);
    vz = vz > 0.f ? vz : expm1f(vz);
    vw = vw > 0.f ? vw : expm1f(vw);
    float4 o = make_float4(vx + wp.x, vy + wp.y, vz + wp.z, vw + wp.w);
    ((float4*)ti)[((size_t)n * T_ + t) * 32 + lane] = o;
}

// ---------------- temporal attention ----------------
__global__ __launch_bounds__(256) void attn_kernel(const float* __restrict__ Q,
                                                   const float* __restrict__ K,
                                                   const float* __restrict__ V,
                                                   const float* __restrict__ ti,
                                                   float* __restrict__ out) {
    __shared__ float sb[8][384];
    int warp = threadIdx.x >> 5, lane = threadIdx.x & 31;
    int task = blockIdx.x * 8 + warp;
    int n = task >> 3, h = task & 7;
    int t4 = lane >> 2;
    int r4 = (n * T_ + t4) * 32 + h * 4 + (lane & 3);
    float* sq = sb[warp];
    float* sk = sq + 128;
    float* sv = sq + 256;
    ((float4*)sq)[lane] = ((const float4*)Q)[(size_t)r4];
    ((float4*)sk)[lane] = ((const float4*)K)[(size_t)r4];
    ((float4*)sv)[lane] = ((const float4*)V)[(size_t)r4];
    __syncwarp();
    if (lane < 8) {
        int t = lane;
        float q[16];
#pragma unroll
        for (int j = 0; j < 16; j++) q[j] = sq[t * 16 + j];
        float p[8];
        float mx = -1e30f;
#pragma unroll
        for (int s = 0; s < 8; s++) {
            float d = 0.f;
#pragma unroll
            for (int j = 0; j < 16; j++) d += q[j] * sk[s * 16 + j];
            d *= 0.25f;
            p[s] = d;
            if (s <= t && d > mx) mx = d;
        }
        float sum = 0.f;
#pragma unroll
        for (int s = 0; s < 8; s++) {
            float e = (s <= t) ? __expf(p[s] - mx) : 0.f;
            p[s] = e;
            sum += e;
        }
        float inv = 1.f / sum;
        float o[16];
#pragma unroll
        for (int j = 0; j < 16; j++) o[j] = 0.f;
#pragma unroll
        for (int s = 0; s < 8; s++) {
            float e = p[s];
#pragma unroll
            for (int j = 0; j < 16; j++) o[j] += e * sv[s * 16 + j];
        }
        size_t base = (size_t)(n * T_ + t) * 128 + h * 16;
#pragma unroll
        for (int j4 = 0; j4 < 4; j4++) {
            float4 tv = ((const float4*)(ti + base))[j4];
            float4 ov = make_float4(o[j4 * 4 + 0] * inv + tv.x,
                                    o[j4 * 4 + 1] * inv + tv.y,
                                    o[j4 * 4 + 2] * inv + tv.z,
                                    o[j4 * 4 + 3] * inv + tv.w);
            ((float4*)(out + base))[j4] = ov;
        }
    }
}

// ---------------- host ----------------
extern "C" void kernel_launch(void* const* d_in, const int* in_sizes, int n_in,
                              void* d_out, int out_size) {
    const float* features  = (const float*)d_in[0];
    const int*   edge_idx  = (const int*)d_in[1];
    const float* edge_vals = (const float*)d_in[2];
    const float* W_s       = (const float*)d_in[3];
    const float* a_s       = (const float*)d_in[4];
    const float* Wq        = (const float*)d_in[5];
    const float* Wkk       = (const float*)d_in[6];
    const float* Wv        = (const float*)d_in[7];
    const float* Wp        = (const float*)d_in[8];
    float* out = (float*)d_out;

    float* pool = nullptr;
    cudaGetSymbolAddress((void**)&pool, g_pool);
    float* H   = pool + OFF_H;
    float* TI  = pool + OFF_TI;
    float* Qb  = pool + OFF_Q;
    float* Kb  = pool + OFF_K;
    float* Vb  = pool + OFF_V;
    float* ps  = pool + OFF_PS;
    float* pd  = pool + OFF_PD;
    int2*  csr    = (int2*)(pool + OFF_CSR);
    int*   offs   = (int*)(pool + OFF_OFFS);
    int*   cursor = (int*)(pool + OFF_CUR);
    int*   bsum   = (int*)(pool + OFF_BS);
    __nv_bfloat16* Bimg = (__nv_bfloat16*)(pool + OFF_BIMG);

    cudaFuncSetAttribute(gemm_w, cudaFuncAttributeMaxDynamicSharedMemorySize, GEMM_SMEM_BYTES);

    const int nb_scan = (int)((RN + 1023) / 1024);
    const int GGRID = 400000 / MROWS;                  // 3125

    // launch order: capture index 3 = gemm_w single-mat (ncu profiles ~index 3)
    prep_bconv<<<512, 256>>>(W_s, Wq, Wkk, Wv, Bimg);                       // 0
    zero_int<<<(int)((RN + 255) / 256), 256>>>(cursor, (int)RN);            // 1
    hist_kernel<<<(T_ * E_) / 256, 256>>>(edge_idx, cursor);                // 2
    gemm_w<<<GGRID, 512, GEMM_SMEM_BYTES>>>(features, Bimg, H, nullptr, nullptr, 0, 1);  // 3
    scan_block<<<nb_scan, 1024>>>(cursor, offs, bsum);                      // 4
    scan_bsum<<<1, 512>>>(bsum, nb_scan);                                   // 5
    scan_add<<<(int)((RN + 255) / 256), 256>>>(offs, bsum, cursor);         // 6
    scatter_kernel<<<(T_ * E_) / 256, 256>>>(edge_idx, edge_vals, cursor, csr);  // 7

    for (int ell = 0; ell < L_; ell++) {
        if (ell) {
            gemm_w<<<GGRID, 512, GEMM_SMEM_BYTES>>>((const float*)out,
                                                    Bimg + (size_t)ell * 32768,
                                                    H, nullptr, nullptr, 1, 1);
        }
        pspd_kernel<<<50000, 256>>>(H, a_s + ell * 256, ps, pd);
        gat_agg_kernel<<<50000, 256>>>(offs, csr, H, ps, pd, Wp + ell * (T_ * D_), TI);
        // fused Q,K,V: A loaded/converted once, 3 B matrices cycled through smem
        gemm_w<<<GGRID, 512, GEMM_SMEM_BYTES>>>(TI, Bimg + (size_t)(2 + ell * 3) * 32768,
                                                Qb, Kb, Vb, 0, 3);
        attn_kernel<<<50000, 256>>>(Qb, Kb, Vb, TI, out);
    }
}

// round 13
// speedup vs baseline: 1.0734x; 1.0373x over previous
#include <cuda_runtime.h>
#include <cuda_bf16.h>
#include <mma.h>
#include <cstdint>

using namespace nvcuda;

#define T_ 8
#define N_ 50000
#define D_ 128
#define E_ 800000
#define L_ 2
#define SH_ 8
#define FH_ 16

// ---------------- scratch pool (static device memory; no allocs) ----------------
constexpr size_t BIG    = (size_t)T_ * N_ * D_;    // 51,200,000 floats
constexpr size_t SMALLV = (size_t)T_ * N_ * SH_;   // 3,200,000 floats
constexpr size_t RN     = (size_t)T_ * N_;         // 400,000 rows
constexpr size_t OFF_H    = 0;
constexpr size_t OFF_TI   = BIG;
constexpr size_t OFF_Q    = 2 * BIG;
constexpr size_t OFF_K    = 3 * BIG;
constexpr size_t OFF_V    = 4 * BIG;
constexpr size_t OFF_PS   = 5 * BIG;
constexpr size_t OFF_PD   = OFF_PS + SMALLV;
constexpr size_t OFF_CSR  = OFF_PD + SMALLV;               // int2 per edge
constexpr size_t OFF_OFFS = OFF_CSR + 2 * (size_t)T_ * E_; // int offsets [RN+1]
constexpr size_t OFF_CUR  = OFF_OFFS + RN + 8;
constexpr size_t OFF_BS   = OFF_CUR + RN + 8;
constexpr size_t OFF_BIMG = OFF_BS + 512;                  // 8 mats x (16384 hi + 16384 lo) bf16
constexpr size_t POOL_SZ  = OFF_BIMG + 131072;

__device__ __align__(256) float g_pool[POOL_SZ];

// ---------------- weight conversion: 8 matrices -> row-major [k][n] bf16 hi/lo ----------------
// g: 0..1 = GAT layer (B[k][n] = W_s[ell][n>>4][k][n&15]); 2+ell*3+{0,1,2} = Q/K/V (B[k][n] = W[ell][k][n])
__global__ void prep_bconv(const float* __restrict__ Ws_, const float* __restrict__ Wq,
                           const float* __restrict__ Wk, const float* __restrict__ Wv,
                           __nv_bfloat16* __restrict__ Bimg) {
    int i = blockIdx.x * 256 + threadIdx.x;            // < 131072 = 8*16384
    int g = i >> 14, idx = i & 16383;
    int k = idx >> 7, n = idx & 127;
    float val;
    if (g < 2) {
        val = Ws_[g * 16384 + (n >> 4) * 2048 + k * 16 + (n & 15)];
    } else {
        int m = g - 2, ell = m / 3, sel = m % 3;
        const float* W = sel == 0 ? Wq : (sel == 1 ? Wk : Wv);
        val = W[ell * 16384 + k * 128 + n];
    }
    __nv_bfloat16 hi = __float2bfloat16_rn(val);
    __nv_bfloat16 lo = __float2bfloat16_rn(val - __bfloat162float(hi));
    Bimg[(size_t)g * 32768 + idx] = hi;
    Bimg[(size_t)g * 32768 + 16384 + idx] = lo;
}

// ---------------- tensor-core GEMM via wmma (HMMA; tcgen05 blocked by compile target) -------
// C_m[400000][128] = X[400000][128] @ W_m[128][128], m < nmats (A converted once, B cycled).
// Split-fp32: D = Ahi*Bhi + Ahi*Blo + Alo*Bhi.
// Geometry: 256 threads, CTA tile 64x128, warp tile 32x32 (2 rb x 4 cq) -> 2 CTAs/SM
// (prologue/mainloop overlap across CTAs) + MMA:frag-load ratio 1.5, ~80 regs (no spills).
// When aatt != nullptr (GAT projection, nmats==1): stage acc through smem, write H
// coalesced, and compute fused ps/pd epilogue (deletes the pspd kernel + its H re-read).
constexpr int LDA = 136;                               // padded smem leading dim (bf16 elems)
constexpr int GEMM_SMEM_BYTES = (2 * 64 * LDA + 2 * 128 * LDA) * 2;  // 104448

__global__ __launch_bounds__(256, 2) void gemm_w(const float* __restrict__ X,
                                                 const __nv_bfloat16* __restrict__ Bm,
                                                 float* __restrict__ C0,
                                                 float* __restrict__ C1,
                                                 float* __restrict__ C2,
                                                 int xmode, int nmats,
                                                 float* __restrict__ ps,
                                                 float* __restrict__ pd,
                                                 const float* __restrict__ aatt) {
    extern __shared__ __nv_bfloat16 sm[];
    __nv_bfloat16* Ah = sm;                            // 64*LDA
    __nv_bfloat16* Al = Ah + 64 * LDA;                 // 64*LDA
    __nv_bfloat16* Bh = Al + 64 * LDA;                 // 128*LDA
    __nv_bfloat16* Bl = Bh + 128 * LDA;                // 128*LDA
    const int tid = threadIdx.x;

    // A tile: load 64 rows fp32, convert to bf16 hi/lo (once per CTA)
    size_t row0 = (size_t)blockIdx.x * 64;
    for (int p = tid; p < 2048; p += 256) {            // p = r*32 + c4
        int r = p >> 5, c4 = p & 31;
        size_t gr = row0 + r;
        size_t srow = xmode ? ((gr % N_) * T_ + gr / N_) : gr;
        float4 v = ((const float4*)X)[srow * 32 + c4];
        __nv_bfloat16 h0 = __float2bfloat16_rn(v.x), h1 = __float2bfloat16_rn(v.y);
        __nv_bfloat16 h2 = __float2bfloat16_rn(v.z), h3 = __float2bfloat16_rn(v.w);
        __nv_bfloat162 hp0(h0, h1), hp1(h2, h3);
        __nv_bfloat162 lp0 = __floats2bfloat162_rn(v.x - __bfloat162float(h0),
                                                   v.y - __bfloat162float(h1));
        __nv_bfloat162 lp1 = __floats2bfloat162_rn(v.z - __bfloat162float(h2),
                                                   v.w - __bfloat162float(h3));
        uint2 hw, lw;
        hw.x = *(uint32_t*)&hp0; hw.y = *(uint32_t*)&hp1;
        lw.x = *(uint32_t*)&lp0; lw.y = *(uint32_t*)&lp1;
        *(uint2*)(Ah + r * LDA + c4 * 4) = hw;
        *(uint2*)(Al + r * LDA + c4 * 4) = lw;
    }

    // warp w: row-block rb = w>>2 (32 rows), col-quarter cq = w&3 (32 cols)
    int w = tid >> 5;
    int rb = w >> 2, cq = w & 3;
    const int arow0 = rb * 32;
    const int col0 = cq * 32;

    for (int m = 0; m < nmats; m++) {
        // B_m hi/lo -> smem (row-major [k][128], padded rows)
        const uint4* bsrc = (const uint4*)(Bm + (size_t)m * 32768);
        for (int p = tid; p < 2048; p += 256) {        // p = k*16 + c (8 bf16 per uint4)
            int k = p >> 4, c = p & 15;
            *(uint4*)(Bh + k * LDA + c * 8) = bsrc[p];
            *(uint4*)(Bl + k * LDA + c * 8) = bsrc[2048 + p];
        }
        __syncthreads();

        wmma::fragment<wmma::accumulator, 16, 16, 16, float> acc[2][2];
#pragma unroll
        for (int s = 0; s < 2; s++)
#pragma unroll
            for (int c = 0; c < 2; c++) wmma::fill_fragment(acc[s][c], 0.f);

#pragma unroll
        for (int ks = 0; ks < 8; ks++) {
            wmma::fragment<wmma::matrix_a, 16, 16, 16, __nv_bfloat16, wmma::row_major> ah[2], al[2];
#pragma unroll
            for (int s = 0; s < 2; s++) {
                wmma::load_matrix_sync(ah[s], Ah + (arow0 + s * 16) * LDA + ks * 16, LDA);
                wmma::load_matrix_sync(al[s], Al + (arow0 + s * 16) * LDA + ks * 16, LDA);
            }
            wmma::fragment<wmma::matrix_b, 16, 16, 16, __nv_bfloat16, wmma::row_major> bh[2];
#pragma unroll
            for (int c = 0; c < 2; c++)
                wmma::load_matrix_sync(bh[c], Bh + (ks * 16) * LDA + col0 + c * 16, LDA);
#pragma unroll
            for (int s = 0; s < 2; s++)
#pragma unroll
                for (int c = 0; c < 2; c++) wmma::mma_sync(acc[s][c], ah[s], bh[c], acc[s][c]);
#pragma unroll
            for (int s = 0; s < 2; s++)
#pragma unroll
                for (int c = 0; c < 2; c++) wmma::mma_sync(acc[s][c], al[s], bh[c], acc[s][c]);
            wmma::fragment<wmma::matrix_b, 16, 16, 16, __nv_bfloat16, wmma::row_major> bl[2];
#pragma unroll
            for (int c = 0; c < 2; c++)
                wmma::load_matrix_sync(bl[c], Bl + (ks * 16) * LDA + col0 + c * 16, LDA);
#pragma unroll
            for (int s = 0; s < 2; s++)
#pragma unroll
                for (int c = 0; c < 2; c++) wmma::mma_sync(acc[s][c], ah[s], bl[c], acc[s][c]);
        }

        if (aatt == nullptr) {
            float* Cm = (m == 0) ? C0 : (m == 1 ? C1 : C2);
#pragma unroll
            for (int s = 0; s < 2; s++)
#pragma unroll
                for (int c = 0; c < 2; c++) {
                    wmma::store_matrix_sync(Cm + (row0 + arow0 + s * 16) * 128 + col0 + c * 16,
                                            acc[s][c], 128, wmma::mem_row_major);
                }
            if (m + 1 < nmats) __syncthreads();        // protect B smem before next fill
        } else {
            // fused epilogue (nmats==1): stage acc via smem (A regions dead), write H
            // coalesced, compute ps/pd per (row, head) -- warp quarter covers heads 2cq,2cq+1
            __syncthreads();                           // all warps done reading A smem
            float* Cs = (float*)sm;                    // 64 x 136 floats = 34816B <= A regions
#pragma unroll
            for (int s = 0; s < 2; s++)
#pragma unroll
                for (int c = 0; c < 2; c++) {
                    wmma::store_matrix_sync(Cs + (arow0 + s * 16) * 136 + col0 + c * 16,
                                            acc[s][c], 136, wmma::mem_row_major);
                }
            __syncthreads();
            // coalesced H write
            for (int p = tid; p < 2048; p += 256) {    // p = r*32 + c4
                int r = p >> 5, c4 = p & 31;
                ((float4*)(C0 + (row0 + r) * 128))[c4] = *(float4*)(Cs + r * 136 + c4 * 4);
            }
            // ps/pd: 64 rows x 8 heads
            for (int q = tid; q < 512; q += 256) {
                int r = q >> 3, h = q & 7;
                const float* cp = Cs + r * 136 + h * 16;
                const float* av = aatt + h * 32;
                float s = 0.f, d = 0.f;
#pragma unroll
                for (int f = 0; f < 16; f++) {
                    float hv = cp[f];
                    s += hv * av[f];
                    d += hv * av[16 + f];
                }
                size_t rr = (row0 + r) * 8 + h;
                ps[rr] = s;
                pd[rr] = d;
            }
        }
    }
}

// ---------------- CSR build ----------------
__global__ void zero_int(int* __restrict__ p, int n) {
    int i = blockIdx.x * 256 + threadIdx.x;
    if (i < n) p[i] = 0;
}

__global__ void hist_kernel(const int* __restrict__ eidx, int* __restrict__ counts) {
    int gid = blockIdx.x * 256 + threadIdx.x;
    int t = gid / E_, e = gid - t * E_;
    int src = eidx[(size_t)t * 2 * E_ + e];
    atomicAdd(counts + t * N_ + src, 1);
}

__global__ __launch_bounds__(1024) void scan_block(const int* __restrict__ counts,
                                                   int* __restrict__ offs,
                                                   int* __restrict__ bsum) {
    __shared__ int s[1024];
    int tid = threadIdx.x;
    int i = blockIdx.x * 1024 + tid;
    int v = (i < (int)RN) ? counts[i] : 0;
    s[tid] = v;
    __syncthreads();
#pragma unroll
    for (int off = 1; off < 1024; off <<= 1) {
        int x = (tid >= off) ? s[tid - off] : 0;
        __syncthreads();
        s[tid] += x;
        __syncthreads();
    }
    if (i < (int)RN) offs[i] = s[tid] - v;
    if (tid == 1023) bsum[blockIdx.x] = s[1023];
}

__global__ __launch_bounds__(512) void scan_bsum(int* __restrict__ bsum, int nb) {
    __shared__ int s[512];
    int tid = threadIdx.x;
    int v = (tid < nb) ? bsum[tid] : 0;
    s[tid] = v;
    __syncthreads();
#pragma unroll
    for (int off = 1; off < 512; off <<= 1) {
        int x = (tid >= off) ? s[tid - off] : 0;
        __syncthreads();
        s[tid] += x;
        __syncthreads();
    }
    if (tid < nb) bsum[tid] = s[tid] - v;
}

__global__ void scan_add(int* __restrict__ offs, const int* __restrict__ bsum,
                         int* __restrict__ cursor) {
    int i = blockIdx.x * 256 + threadIdx.x;
    if (i < (int)RN) {
        int o = offs[i] + bsum[i >> 10];
        offs[i] = o;
        cursor[i] = o;
        if (i == 0) offs[RN] = T_ * E_;
    }
}

__global__ void scatter_kernel(const int* __restrict__ eidx, const float* __restrict__ evals,
                               int* __restrict__ cursor, int2* __restrict__ csr) {
    int gid = blockIdx.x * 256 + threadIdx.x;
    int t = gid / E_, e = gid - t * E_;
    const int* ei = eidx + (size_t)t * 2 * E_;
    int src = ei[e];
    int dst = ei[E_ + e];
    int pos = atomicAdd(cursor + t * N_ + src, 1);
    csr[pos] = make_int2(dst, __float_as_int(evals[(size_t)t * E_ + e]));
}

// ---------------- fused GAT aggregate + normalize + ELU + transpose + Wp -> ti ----------------
__global__ __launch_bounds__(256) void gat_agg_kernel(const int* __restrict__ offs,
                                                      const int2* __restrict__ csr,
                                                      const float* __restrict__ H,
                                                      const float* __restrict__ ps,
                                                      const float* __restrict__ pd,
                                                      const float* __restrict__ Wp,
                                                      float* __restrict__ ti) {
    int r = blockIdx.x * 8 + (threadIdx.x >> 5);
    int lane = threadIdx.x & 31;
    int h = lane >> 2;
    int t = r / N_;
    int n = r - t * N_;
    int beg = offs[r], end = offs[r + 1];
    float psv = __ldg(ps + r * 8 + h);
    float4 acc = make_float4(0.f, 0.f, 0.f, 0.f);
    float esum = 0.f;
    const int tbase = t * N_;

    int2 cur = csr[beg];
    for (int j = beg; j < end; j++) {
        int2 nxt = make_int2(0, 0);
        if (j + 1 < end) nxt = csr[j + 1];
        int rd = tbase + cur.x;
        float w = __int_as_float(cur.y);
        float pdv = __ldg(pd + rd * 8 + h);
        float4 hv = ((const float4*)H)[(size_t)rd * 32 + lane];
        float sc = w * (psv + pdv);
        sc = sc > 0.f ? sc : 0.2f * sc;
        float ev = __expf(sc);
        esum += ev;
        acc.x += ev * hv.x;
        acc.y += ev * hv.y;
        acc.z += ev * hv.z;
        acc.w += ev * hv.w;
        cur = nxt;
    }
    float inv = 1.f / esum;
    float4 wp = ((const float4*)Wp)[t * 32 + lane];
    float vx = acc.x * inv, vy = acc.y * inv, vz = acc.z * inv, vw = acc.w * inv;
    vx = vx > 0.f ? vx : expm1f(vx);
    vy = vy > 0.f ? vy : expm1f(vy);
    vz = vz > 0.f ? vz : expm1f(vz);
    vw = vw > 0.f ? vw : expm1f(vw);
    float4 o = make_float4(vx + wp.x, vy + wp.y, vz + wp.z, vw + wp.w);
    ((float4*)ti)[((size_t)n * T_ + t) * 32 + lane] = o;
}

// ---------------- temporal attention ----------------
__global__ __launch_bounds__(256) void attn_kernel(const float* __restrict__ Q,
                                                   const float* __restrict__ K,
                                                   const float* __restrict__ V,
                                                   const float* __restrict__ ti,
                                                   float* __restrict__ out) {
    __shared__ float sb[8][384];
    int warp = threadIdx.x >> 5, lane = threadIdx.x & 31;
    int task = blockIdx.x * 8 + warp;
    int n = task >> 3, h = task & 7;
    int t4 = lane >> 2;
    int r4 = (n * T_ + t4) * 32 + h * 4 + (lane & 3);
    float* sq = sb[warp];
    float* sk = sq + 128;
    float* sv = sq + 256;
    ((float4*)sq)[lane] = ((const float4*)Q)[(size_t)r4];
    ((float4*)sk)[lane] = ((const float4*)K)[(size_t)r4];
    ((float4*)sv)[lane] = ((const float4*)V)[(size_t)r4];
    __syncwarp();
    if (lane < 8) {
        int t = lane;
        float q[16];
#pragma unroll
        for (int j = 0; j < 16; j++) q[j] = sq[t * 16 + j];
        float p[8];
        float mx = -1e30f;
#pragma unroll
        for (int s = 0; s < 8; s++) {
            float d = 0.f;
#pragma unroll
            for (int j = 0; j < 16; j++) d += q[j] * sk[s * 16 + j];
            d *= 0.25f;
            p[s] = d;
            if (s <= t && d > mx) mx = d;
        }
        float sum = 0.f;
#pragma unroll
        for (int s = 0; s < 8; s++) {
            float e = (s <= t) ? __expf(p[s] - mx) : 0.f;
            p[s] = e;
            sum += e;
        }
        float inv = 1.f / sum;
        float o[16];
#pragma unroll
        for (int j = 0; j < 16; j++) o[j] = 0.f;
#pragma unroll
        for (int s = 0; s < 8; s++) {
            float e = p[s];
#pragma unroll
            for (int j = 0; j < 16; j++) o[j] += e * sv[s * 16 + j];
        }
        size_t base = (size_t)(n * T_ + t) * 128 + h * 16;
#pragma unroll
        for (int j4 = 0; j4 < 4; j4++) {
            float4 tv = ((const float4*)(ti + base))[j4];
            float4 ov = make_float4(o[j4 * 4 + 0] * inv + tv.x,
                                    o[j4 * 4 + 1] * inv + tv.y,
                                    o[j4 * 4 + 2] * inv + tv.z,
                                    o[j4 * 4 + 3] * inv + tv.w);
            ((float4*)(out + base))[j4] = ov;
        }
    }
}

// ---------------- host ----------------
extern "C" void kernel_launch(void* const* d_in, const int* in_sizes, int n_in,
                              void* d_out, int out_size) {
    const float* features  = (const float*)d_in[0];
    const int*   edge_idx  = (const int*)d_in[1];
    const float* edge_vals = (const float*)d_in[2];
    const float* W_s       = (const float*)d_in[3];
    const float* a_s       = (const float*)d_in[4];
    const float* Wq        = (const float*)d_in[5];
    const float* Wkk       = (const float*)d_in[6];
    const float* Wv        = (const float*)d_in[7];
    const float* Wp        = (const float*)d_in[8];
    float* out = (float*)d_out;

    float* pool = nullptr;
    cudaGetSymbolAddress((void**)&pool, g_pool);
    float* H   = pool + OFF_H;
    float* TI  = pool + OFF_TI;
    float* Qb  = pool + OFF_Q;
    float* Kb  = pool + OFF_K;
    float* Vb  = pool + OFF_V;
    float* ps  = pool + OFF_PS;
    float* pd  = pool + OFF_PD;
    int2*  csr    = (int2*)(pool + OFF_CSR);
    int*   offs   = (int*)(pool + OFF_OFFS);
    int*   cursor = (int*)(pool + OFF_CUR);
    int*   bsum   = (int*)(pool + OFF_BS);
    __nv_bfloat16* Bimg = (__nv_bfloat16*)(pool + OFF_BIMG);

    cudaFuncSetAttribute(gemm_w, cudaFuncAttributeMaxDynamicSharedMemorySize, GEMM_SMEM_BYTES);

    const int nb_scan = (int)((RN + 1023) / 1024);
    const int GGRID = 400000 / 64;                     // 6250

    // launch order: capture index 3 = gemm_w GAT projection (ncu profiles ~index 3)
    prep_bconv<<<512, 256>>>(W_s, Wq, Wkk, Wv, Bimg);                       // 0
    zero_int<<<(int)((RN + 255) / 256), 256>>>(cursor, (int)RN);            // 1
    hist_kernel<<<(T_ * E_) / 256, 256>>>(edge_idx, cursor);                // 2
    gemm_w<<<GGRID, 256, GEMM_SMEM_BYTES>>>(features, Bimg, H, nullptr, nullptr,
                                            0, 1, ps, pd, a_s);             // 3 (fused ps/pd)
    scan_block<<<nb_scan, 1024>>>(cursor, offs, bsum);                      // 4
    scan_bsum<<<1, 512>>>(bsum, nb_scan);                                   // 5
    scan_add<<<(int)((RN + 255) / 256), 256>>>(offs, bsum, cursor);         // 6
    scatter_kernel<<<(T_ * E_) / 256, 256>>>(edge_idx, edge_vals, cursor, csr);  // 7

    for (int ell = 0; ell < L_; ell++) {
        if (ell) {
            gemm_w<<<GGRID, 256, GEMM_SMEM_BYTES>>>((const float*)out,
                                                    Bimg + (size_t)ell * 32768,
                                                    H, nullptr, nullptr, 1, 1,
                                                    ps, pd, a_s + ell * 256);
        }
        gat_agg_kernel<<<50000, 256>>>(offs, csr, H, ps, pd, Wp + ell * (T_ * D_), TI);
        // fused Q,K,V: A loaded/converted once, 3 B matrices cycled through smem
        gemm_w<<<GGRID, 256, GEMM_SMEM_BYTES>>>(TI, Bimg + (size_t)(2 + ell * 3) * 32768,
                                                Qb, Kb, Vb, 0, 3,
                                                nullptr, nullptr, nullptr);
        attn_kernel<<<50000, 256>>>(Qb, Kb, Vb, TI, out);
    }
}

// round 14
// speedup vs baseline: 1.1692x; 1.0893x over previous
#include <cuda_runtime.h>
#include <cuda_bf16.h>
#include <mma.h>
#include <cstdint>

using namespace nvcuda;

#define T_ 8
#define N_ 50000
#define D_ 128
#define E_ 800000
#define L_ 2
#define SH_ 8
#define FH_ 16

// ---------------- scratch pool (static device memory; no allocs) ----------------
constexpr size_t BIG    = (size_t)T_ * N_ * D_;    // 51,200,000 floats
constexpr size_t SMALLV = (size_t)T_ * N_ * SH_;   // 3,200,000 floats
constexpr size_t RN     = (size_t)T_ * N_;         // 400,000 rows
constexpr size_t OFF_H    = 0;
constexpr size_t OFF_TI   = BIG;
constexpr size_t OFF_Q    = 2 * BIG;
constexpr size_t OFF_K    = 3 * BIG;
constexpr size_t OFF_V    = 4 * BIG;
constexpr size_t OFF_PS   = 5 * BIG;
constexpr size_t OFF_PD   = OFF_PS + SMALLV;
constexpr size_t OFF_CSR  = OFF_PD + SMALLV;               // int2 per edge
constexpr size_t OFF_OFFS = OFF_CSR + 2 * (size_t)T_ * E_; // int offsets [RN+1]
constexpr size_t OFF_CUR  = OFF_OFFS + RN + 8;
constexpr size_t OFF_BS   = OFF_CUR + RN + 8;
constexpr size_t OFF_BIMG = OFF_BS + 512;                  // 8 mats x (16384 hi + 16384 lo) bf16
constexpr size_t POOL_SZ  = OFF_BIMG + 131072;

__device__ __align__(256) float g_pool[POOL_SZ];

// ---------------- weight conversion: 8 matrices -> row-major [k][n] bf16 hi/lo ----------------
// g: 0..1 = GAT layer (B[k][n] = W_s[ell][n>>4][k][n&15]); 2+ell*3+{0,1,2} = Q/K/V (B[k][n] = W[ell][k][n])
__global__ void prep_bconv(const float* __restrict__ Ws_, const float* __restrict__ Wq,
                           const float* __restrict__ Wk, const float* __restrict__ Wv,
                           __nv_bfloat16* __restrict__ Bimg) {
    int i = blockIdx.x * 256 + threadIdx.x;            // < 131072 = 8*16384
    int g = i >> 14, idx = i & 16383;
    int k = idx >> 7, n = idx & 127;
    float val;
    if (g < 2) {
        val = Ws_[g * 16384 + (n >> 4) * 2048 + k * 16 + (n & 15)];
    } else {
        int m = g - 2, ell = m / 3, sel = m % 3;
        const float* W = sel == 0 ? Wq : (sel == 1 ? Wk : Wv);
        val = W[ell * 16384 + k * 128 + n];
    }
    __nv_bfloat16 hi = __float2bfloat16_rn(val);
    __nv_bfloat16 lo = __float2bfloat16_rn(val - __bfloat162float(hi));
    Bimg[(size_t)g * 32768 + idx] = hi;
    Bimg[(size_t)g * 32768 + 16384 + idx] = lo;
}

// ---------------- tensor-core GEMM via wmma (HMMA; tcgen05 blocked by compile target) -------
// C_m[400000][128] = X[400000][128] @ W_m[128][128], m < nmats (A converted once, B cycled).
// Split-fp32: D = Ahi*Bhi + Ahi*Blo + Alo*Bhi.
// Geometry: 256 threads, CTA tile 64x128, warp tile 32x32 (2 rb x 4 cq) -> 2 CTAs/SM.
// When aatt != nullptr (GAT projection, nmats==1): fused ps/pd epilogue via smem staging.
constexpr int LDA = 136;                               // padded smem leading dim (bf16 elems)
constexpr int GEMM_SMEM_BYTES = (2 * 64 * LDA + 2 * 128 * LDA) * 2;  // 104448

__global__ __launch_bounds__(256, 2) void gemm_w(const float* __restrict__ X,
                                                 const __nv_bfloat16* __restrict__ Bm,
                                                 float* __restrict__ C0,
                                                 float* __restrict__ C1,
                                                 float* __restrict__ C2,
                                                 int xmode, int nmats,
                                                 float* __restrict__ ps,
                                                 float* __restrict__ pd,
                                                 const float* __restrict__ aatt) {
    extern __shared__ __nv_bfloat16 sm[];
    __nv_bfloat16* Ah = sm;                            // 64*LDA
    __nv_bfloat16* Al = Ah + 64 * LDA;                 // 64*LDA
    __nv_bfloat16* Bh = Al + 64 * LDA;                 // 128*LDA
    __nv_bfloat16* Bl = Bh + 128 * LDA;                // 128*LDA
    const int tid = threadIdx.x;

    // A tile: load 64 rows fp32, convert to bf16 hi/lo (once per CTA)
    size_t row0 = (size_t)blockIdx.x * 64;
    for (int p = tid; p < 2048; p += 256) {            // p = r*32 + c4
        int r = p >> 5, c4 = p & 31;
        size_t gr = row0 + r;
        size_t srow = xmode ? ((gr % N_) * T_ + gr / N_) : gr;
        float4 v = ((const float4*)X)[srow * 32 + c4];
        __nv_bfloat16 h0 = __float2bfloat16_rn(v.x), h1 = __float2bfloat16_rn(v.y);
        __nv_bfloat16 h2 = __float2bfloat16_rn(v.z), h3 = __float2bfloat16_rn(v.w);
        __nv_bfloat162 hp0(h0, h1), hp1(h2, h3);
        __nv_bfloat162 lp0 = __floats2bfloat162_rn(v.x - __bfloat162float(h0),
                                                   v.y - __bfloat162float(h1));
        __nv_bfloat162 lp1 = __floats2bfloat162_rn(v.z - __bfloat162float(h2),
                                                   v.w - __bfloat162float(h3));
        uint2 hw, lw;
        hw.x = *(uint32_t*)&hp0; hw.y = *(uint32_t*)&hp1;
        lw.x = *(uint32_t*)&lp0; lw.y = *(uint32_t*)&lp1;
        *(uint2*)(Ah + r * LDA + c4 * 4) = hw;
        *(uint2*)(Al + r * LDA + c4 * 4) = lw;
    }

    // warp w: row-block rb = w>>2 (32 rows), col-quarter cq = w&3 (32 cols)
    int w = tid >> 5;
    int rb = w >> 2, cq = w & 3;
    const int arow0 = rb * 32;
    const int col0 = cq * 32;

    for (int m = 0; m < nmats; m++) {
        // B_m hi/lo -> smem (row-major [k][128], padded rows)
        const uint4* bsrc = (const uint4*)(Bm + (size_t)m * 32768);
        for (int p = tid; p < 2048; p += 256) {        // p = k*16 + c (8 bf16 per uint4)
            int k = p >> 4, c = p & 15;
            *(uint4*)(Bh + k * LDA + c * 8) = bsrc[p];
            *(uint4*)(Bl + k * LDA + c * 8) = bsrc[2048 + p];
        }
        __syncthreads();

        wmma::fragment<wmma::accumulator, 16, 16, 16, float> acc[2][2];
#pragma unroll
        for (int s = 0; s < 2; s++)
#pragma unroll
            for (int c = 0; c < 2; c++) wmma::fill_fragment(acc[s][c], 0.f);

#pragma unroll
        for (int ks = 0; ks < 8; ks++) {
            wmma::fragment<wmma::matrix_a, 16, 16, 16, __nv_bfloat16, wmma::row_major> ah[2], al[2];
#pragma unroll
            for (int s = 0; s < 2; s++) {
                wmma::load_matrix_sync(ah[s], Ah + (arow0 + s * 16) * LDA + ks * 16, LDA);
                wmma::load_matrix_sync(al[s], Al + (arow0 + s * 16) * LDA + ks * 16, LDA);
            }
            wmma::fragment<wmma::matrix_b, 16, 16, 16, __nv_bfloat16, wmma::row_major> bh[2];
#pragma unroll
            for (int c = 0; c < 2; c++)
                wmma::load_matrix_sync(bh[c], Bh + (ks * 16) * LDA + col0 + c * 16, LDA);
#pragma unroll
            for (int s = 0; s < 2; s++)
#pragma unroll
                for (int c = 0; c < 2; c++) wmma::mma_sync(acc[s][c], ah[s], bh[c], acc[s][c]);
#pragma unroll
            for (int s = 0; s < 2; s++)
#pragma unroll
                for (int c = 0; c < 2; c++) wmma::mma_sync(acc[s][c], al[s], bh[c], acc[s][c]);
            wmma::fragment<wmma::matrix_b, 16, 16, 16, __nv_bfloat16, wmma::row_major> bl[2];
#pragma unroll
            for (int c = 0; c < 2; c++)
                wmma::load_matrix_sync(bl[c], Bl + (ks * 16) * LDA + col0 + c * 16, LDA);
#pragma unroll
            for (int s = 0; s < 2; s++)
#pragma unroll
                for (int c = 0; c < 2; c++) wmma::mma_sync(acc[s][c], ah[s], bl[c], acc[s][c]);
        }

        if (aatt == nullptr) {
            float* Cm = (m == 0) ? C0 : (m == 1 ? C1 : C2);
#pragma unroll
            for (int s = 0; s < 2; s++)
#pragma unroll
                for (int c = 0; c < 2; c++) {
                    wmma::store_matrix_sync(Cm + (row0 + arow0 + s * 16) * 128 + col0 + c * 16,
                                            acc[s][c], 128, wmma::mem_row_major);
                }
            if (m + 1 < nmats) __syncthreads();        // protect B smem before next fill
        } else {
            // fused epilogue (nmats==1): stage acc via smem (A regions dead), write H
            // coalesced, compute ps/pd per (row, head)
            __syncthreads();                           // all warps done reading A smem
            float* Cs = (float*)sm;                    // 64 x 136 floats <= A regions
#pragma unroll
            for (int s = 0; s < 2; s++)
#pragma unroll
                for (int c = 0; c < 2; c++) {
                    wmma::store_matrix_sync(Cs + (arow0 + s * 16) * 136 + col0 + c * 16,
                                            acc[s][c], 136, wmma::mem_row_major);
                }
            __syncthreads();
            for (int p = tid; p < 2048; p += 256) {    // coalesced H write
                int r = p >> 5, c4 = p & 31;
                ((float4*)(C0 + (row0 + r) * 128))[c4] = *(float4*)(Cs + r * 136 + c4 * 4);
            }
            for (int q = tid; q < 512; q += 256) {     // ps/pd: 64 rows x 8 heads
                int r = q >> 3, h = q & 7;
                const float* cp = Cs + r * 136 + h * 16;
                const float* av = aatt + h * 32;
                float s = 0.f, d = 0.f;
#pragma unroll
                for (int f = 0; f < 16; f++) {
                    float hv = cp[f];
                    s += hv * av[f];
                    d += hv * av[16 + f];
                }
                size_t rr = (row0 + r) * 8 + h;
                ps[rr] = s;
                pd[rr] = d;
            }
        }
    }
}

// ---------------- CSR build ----------------
__global__ void zero_int(int* __restrict__ p, int n) {
    int i = blockIdx.x * 256 + threadIdx.x;
    if (i < n) p[i] = 0;
}

__global__ void hist_kernel(const int* __restrict__ eidx, int* __restrict__ counts) {
    int gid = blockIdx.x * 256 + threadIdx.x;
    int t = gid / E_, e = gid - t * E_;
    int src = eidx[(size_t)t * 2 * E_ + e];
    atomicAdd(counts + t * N_ + src, 1);
}

__global__ __launch_bounds__(1024) void scan_block(const int* __restrict__ counts,
                                                   int* __restrict__ offs,
                                                   int* __restrict__ bsum) {
    __shared__ int s[1024];
    int tid = threadIdx.x;
    int i = blockIdx.x * 1024 + tid;
    int v = (i < (int)RN) ? counts[i] : 0;
    s[tid] = v;
    __syncthreads();
#pragma unroll
    for (int off = 1; off < 1024; off <<= 1) {
        int x = (tid >= off) ? s[tid - off] : 0;
        __syncthreads();
        s[tid] += x;
        __syncthreads();
    }
    if (i < (int)RN) offs[i] = s[tid] - v;
    if (tid == 1023) bsum[blockIdx.x] = s[1023];
}

__global__ __launch_bounds__(512) void scan_bsum(int* __restrict__ bsum, int nb) {
    __shared__ int s[512];
    int tid = threadIdx.x;
    int v = (tid < nb) ? bsum[tid] : 0;
    s[tid] = v;
    __syncthreads();
#pragma unroll
    for (int off = 1; off < 512; off <<= 1) {
        int x = (tid >= off) ? s[tid - off] : 0;
        __syncthreads();
        s[tid] += x;
        __syncthreads();
    }
    if (tid < nb) bsum[tid] = s[tid] - v;
}

__global__ void scan_add(int* __restrict__ offs, const int* __restrict__ bsum,
                         int* __restrict__ cursor) {
    int i = blockIdx.x * 256 + threadIdx.x;
    if (i < (int)RN) {
        int o = offs[i] + bsum[i >> 10];
        offs[i] = o;
        cursor[i] = o;
        if (i == 0) offs[RN] = T_ * E_;
    }
}

__global__ void scatter_kernel(const int* __restrict__ eidx, const float* __restrict__ evals,
                               int* __restrict__ cursor, int2* __restrict__ csr) {
    int gid = blockIdx.x * 256 + threadIdx.x;
    int t = gid / E_, e = gid - t * E_;
    const int* ei = eidx + (size_t)t * 2 * E_;
    int src = ei[e];
    int dst = ei[E_ + e];
    int pos = atomicAdd(cursor + t * N_ + src, 1);
    csr[pos] = make_int2(dst, __float_as_int(evals[(size_t)t * E_ + e]));
}

// ---------------- fused GAT aggregate + normalize + ELU + transpose + Wp -> ti ----------------
// One warp per row; 4-edge unroll: batch loads (4x csr, 4x pd, 4x H row) before compute
// to raise per-warp MLP ~2 -> ~8 and hide L2/DRAM gather latency.
__global__ __launch_bounds__(256) void gat_agg_kernel(const int* __restrict__ offs,
                                                      const int2* __restrict__ csr,
                                                      const float* __restrict__ H,
                                                      const float* __restrict__ ps,
                                                      const float* __restrict__ pd,
                                                      const float* __restrict__ Wp,
                                                      float* __restrict__ ti) {
    int r = blockIdx.x * 8 + (threadIdx.x >> 5);
    int lane = threadIdx.x & 31;
    int h = lane >> 2;
    int t = r / N_;
    int n = r - t * N_;
    int beg = offs[r], end = offs[r + 1];
    float psv = __ldg(ps + r * 8 + h);
    float4 acc = make_float4(0.f, 0.f, 0.f, 0.f);
    float esum = 0.f;
    const int tbase = t * N_;
    const float4* H4 = (const float4*)H;

    int j = beg;
    for (; j + 4 <= end; j += 4) {
        int2 e0 = __ldg(csr + j);
        int2 e1 = __ldg(csr + j + 1);
        int2 e2 = __ldg(csr + j + 2);
        int2 e3 = __ldg(csr + j + 3);
        int rd0 = tbase + e0.x, rd1 = tbase + e1.x, rd2 = tbase + e2.x, rd3 = tbase + e3.x;
        float p0 = __ldg(pd + rd0 * 8 + h);
        float p1 = __ldg(pd + rd1 * 8 + h);
        float p2 = __ldg(pd + rd2 * 8 + h);
        float p3 = __ldg(pd + rd3 * 8 + h);
        float4 h0 = H4[(size_t)rd0 * 32 + lane];
        float4 h1 = H4[(size_t)rd1 * 32 + lane];
        float4 h2 = H4[(size_t)rd2 * 32 + lane];
        float4 h3 = H4[(size_t)rd3 * 32 + lane];
        float s0 = __int_as_float(e0.y) * (psv + p0);
        float s1 = __int_as_float(e1.y) * (psv + p1);
        float s2 = __int_as_float(e2.y) * (psv + p2);
        float s3 = __int_as_float(e3.y) * (psv + p3);
        s0 = s0 > 0.f ? s0 : 0.2f * s0;
        s1 = s1 > 0.f ? s1 : 0.2f * s1;
        s2 = s2 > 0.f ? s2 : 0.2f * s2;
        s3 = s3 > 0.f ? s3 : 0.2f * s3;
        float v0 = __expf(s0), v1 = __expf(s1), v2 = __expf(s2), v3 = __expf(s3);
        esum += (v0 + v1) + (v2 + v3);
        acc.x += v0 * h0.x + v1 * h1.x + v2 * h2.x + v3 * h3.x;
        acc.y += v0 * h0.y + v1 * h1.y + v2 * h2.y + v3 * h3.y;
        acc.z += v0 * h0.z + v1 * h1.z + v2 * h2.z + v3 * h3.z;
        acc.w += v0 * h0.w + v1 * h1.w + v2 * h2.w + v3 * h3.w;
    }
    for (; j < end; j++) {
        int2 e0 = __ldg(csr + j);
        int rd0 = tbase + e0.x;
        float p0 = __ldg(pd + rd0 * 8 + h);
        float4 h0 = H4[(size_t)rd0 * 32 + lane];
        float s0 = __int_as_float(e0.y) * (psv + p0);
        s0 = s0 > 0.f ? s0 : 0.2f * s0;
        float v0 = __expf(s0);
        esum += v0;
        acc.x += v0 * h0.x;
        acc.y += v0 * h0.y;
        acc.z += v0 * h0.z;
        acc.w += v0 * h0.w;
    }

    float inv = 1.f / esum;
    float4 wp = ((const float4*)Wp)[t * 32 + lane];
    float vx = acc.x * inv, vy = acc.y * inv, vz = acc.z * inv, vw = acc.w * inv;
    vx = vx > 0.f ? vx : expm1f(vx);
    vy = vy > 0.f ? vy : expm1f(vy);
    vz = vz > 0.f ? vz : expm1f(vz);
    vw = vw > 0.f ? vw : expm1f(vw);
    float4 o = make_float4(vx + wp.x, vy + wp.y, vz + wp.z, vw + wp.w);
    ((float4*)ti)[((size_t)n * T_ + t) * 32 + lane] = o;
}

// ---------------- temporal attention: full-warp compute ----------------
// One warp per (node, head). Lane = (t = lane>>2, dim-quarter = lane&3).
// Scores via quartet shfl-reduce; softmax redundantly per quartet; each lane owns 4 dims.
__global__ __launch_bounds__(256) void attn_kernel(const float* __restrict__ Q,
                                                   const float* __restrict__ K,
                                                   const float* __restrict__ V,
                                                   const float* __restrict__ ti,
                                                   float* __restrict__ out) {
    __shared__ float sb[8][384];
    int warp = threadIdx.x >> 5, lane = threadIdx.x & 31;
    int task = blockIdx.x * 8 + warp;
    int n = task >> 3, h = task & 7;
    int t4 = lane >> 2;
    int r4 = (n * T_ + t4) * 32 + h * 4 + (lane & 3);
    float* sq = sb[warp];
    float* sk = sq + 128;
    float* sv = sq + 256;
    ((float4*)sq)[lane] = ((const float4*)Q)[(size_t)r4];
    ((float4*)sk)[lane] = ((const float4*)K)[(size_t)r4];
    ((float4*)sv)[lane] = ((const float4*)V)[(size_t)r4];
    __syncwarp();

    const int tq = lane >> 2, qd = lane & 3;
    float4 q = *(float4*)(sq + tq * 16 + qd * 4);
    float sc[8];
#pragma unroll
    for (int s = 0; s < 8; s++) {
        float4 k = *(float4*)(sk + s * 16 + qd * 4);
        float p = q.x * k.x + q.y * k.y + q.z * k.z + q.w * k.w;
        p += __shfl_xor_sync(0xffffffffu, p, 1);
        p += __shfl_xor_sync(0xffffffffu, p, 2);
        sc[s] = p * 0.25f;                             // 1/sqrt(16)
    }
    float mx = -1e30f;
#pragma unroll
    for (int s = 0; s < 8; s++)
        if (s <= tq && sc[s] > mx) mx = sc[s];
    float sum = 0.f;
#pragma unroll
    for (int s = 0; s < 8; s++) {
        float e = (s <= tq) ? __expf(sc[s] - mx) : 0.f;
        sc[s] = e;
        sum += e;
    }
    float inv = 1.f / sum;
    float4 o = make_float4(0.f, 0.f, 0.f, 0.f);
#pragma unroll
    for (int s = 0; s < 8; s++) {
        float e = sc[s];
        float4 v = *(float4*)(sv + s * 16 + qd * 4);
        o.x += e * v.x;
        o.y += e * v.y;
        o.z += e * v.z;
        o.w += e * v.w;
    }
    size_t base = (size_t)(n * T_ + tq) * 128 + h * 16 + qd * 4;
    float4 tv = *(const float4*)(ti + base);
    *(float4*)(out + base) = make_float4(o.x * inv + tv.x, o.y * inv + tv.y,
                                         o.z * inv + tv.z, o.w * inv + tv.w);
}

// ---------------- host ----------------
extern "C" void kernel_launch(void* const* d_in, const int* in_sizes, int n_in,
                              void* d_out, int out_size) {
    const float* features  = (const float*)d_in[0];
    const int*   edge_idx  = (const int*)d_in[1];
    const float* edge_vals = (const float*)d_in[2];
    const float* W_s       = (const float*)d_in[3];
    const float* a_s       = (const float*)d_in[4];
    const float* Wq        = (const float*)d_in[5];
    const float* Wkk       = (const float*)d_in[6];
    const float* Wv        = (const float*)d_in[7];
    const float* Wp        = (const float*)d_in[8];
    float* out = (float*)d_out;

    float* pool = nullptr;
    cudaGetSymbolAddress((void**)&pool, g_pool);
    float* H   = pool + OFF_H;
    float* TI  = pool + OFF_TI;
    float* Qb  = pool + OFF_Q;
    float* Kb  = pool + OFF_K;
    float* Vb  = pool + OFF_V;
    float* ps  = pool + OFF_PS;
    float* pd  = pool + OFF_PD;
    int2*  csr    = (int2*)(pool + OFF_CSR);
    int*   offs   = (int*)(pool + OFF_OFFS);
    int*   cursor = (int*)(pool + OFF_CUR);
    int*   bsum   = (int*)(pool + OFF_BS);
    __nv_bfloat16* Bimg = (__nv_bfloat16*)(pool + OFF_BIMG);

    cudaFuncSetAttribute(gemm_w, cudaFuncAttributeMaxDynamicSharedMemorySize, GEMM_SMEM_BYTES);

    const int nb_scan = (int)((RN + 1023) / 1024);
    const int GGRID = 400000 / 64;                     // 6250

    // launch order: capture index 3 = gemm_w GAT projection (ncu profiles ~index 3)
    prep_bconv<<<512, 256>>>(W_s, Wq, Wkk, Wv, Bimg);                       // 0
    zero_int<<<(int)((RN + 255) / 256), 256>>>(cursor, (int)RN);            // 1
    hist_kernel<<<(T_ * E_) / 256, 256>>>(edge_idx, cursor);                // 2
    gemm_w<<<GGRID, 256, GEMM_SMEM_BYTES>>>(features, Bimg, H, nullptr, nullptr,
                                            0, 1, ps, pd, a_s);             // 3 (fused ps/pd)
    scan_block<<<nb_scan, 1024>>>(cursor, offs, bsum);                      // 4
    scan_bsum<<<1, 512>>>(bsum, nb_scan);                                   // 5
    scan_add<<<(int)((RN + 255) / 256), 256>>>(offs, bsum, cursor);         // 6
    scatter_kernel<<<(T_ * E_) / 256, 256>>>(edge_idx, edge_vals, cursor, csr);  // 7

    for (int ell = 0; ell < L_; ell++) {
        if (ell) {
            gemm_w<<<GGRID, 256, GEMM_SMEM_BYTES>>>((const float*)out,
                                                    Bimg + (size_t)ell * 32768,
                                                    H, nullptr, nullptr, 1, 1,
                                                    ps, pd, a_s + ell * 256);
        }
        gat_agg_kernel<<<50000, 256>>>(offs, csr, H, ps, pd, Wp + ell * (T_ * D_), TI);
        // fused Q,K,V: A loaded/converted once, 3 B matrices cycled through smem
        gemm_w<<<GGRID, 256, GEMM_SMEM_BYTES>>>(TI, Bimg + (size_t)(2 + ell * 3) * 32768,
                                                Qb, Kb, Vb, 0, 3,
                                                nullptr, nullptr, nullptr);
        attn_kernel<<<50000, 256>>>(Qb, Kb, Vb, TI, out);
    }
}